// round 1
// baseline (speedup 1.0000x reference)
#include <cuda_runtime.h>

// Problem constants (fixed shapes per reference)
#define HH  1024
#define BB  2
#define SS  2048
#define NHH 16
#define HDD 64
#define MT  (BB*SS)   // 4096 total rows

// Scratch (static device globals — allocation-free per harness rules)
__device__ float g_Wd[HH*HH];
__device__ float g_bd[HH];
__device__ float g_D[MT*HH];   // D = x@(Wq-Wk)+(bq-bk), layout [B,S,H]
__device__ float g_V[MT*HH];   // V = x@Wv+bv,           layout [B,S,H]
__device__ float g_C[MT*HH];   // attention context,     layout [B,S,H]

// ---------------------------------------------------------------------------
// Prep: Wd = Wq - Wk, bd = bq - bk
// ---------------------------------------------------------------------------
__global__ void prep_kernel(const float* __restrict__ Wq, const float* __restrict__ Wk,
                            const float* __restrict__ bq, const float* __restrict__ bk) {
    int i = blockIdx.x * blockDim.x + threadIdx.x;
    if (i < HH*HH) g_Wd[i] = Wq[i] - Wk[i];
    if (i < HH)    g_bd[i] = bq[i] - bk[i];
}

// ---------------------------------------------------------------------------
// SGEMM: C[M,N] = A[M,K] @ B[K,N] + bias[N]
// 128x128 block tile, BK=8, 256 threads, 8x8 register tile (split 64+64 halves
// for conflict-free LDS.128).
// Requires M%128==0, N%128==0, K%8==0 (true for all calls here).
// ---------------------------------------------------------------------------
__global__ __launch_bounds__(256) void sgemm_bias(
    const float* __restrict__ A, const float* __restrict__ B,
    const float* __restrict__ bias, float* __restrict__ C,
    int M, int N, int K)
{
    __shared__ __align__(16) float As[8][128];   // [k][m] (transposed)
    __shared__ __align__(16) float Bs[8][128];   // [k][n]

    const int tid = threadIdx.x;
    const int ty  = tid >> 4;        // 0..15
    const int tx  = tid & 15;        // 0..15
    const int rowBase = blockIdx.y * 128;
    const int colBase = blockIdx.x * 128;

    // loaders
    const int aRow = tid >> 1;       // 0..127
    const int aCol = (tid & 1) * 4;  // 0 or 4
    const int bRow = tid >> 5;       // 0..7
    const int bCol = (tid & 31) * 4; // 0..124

    const float* Aptr = A + (size_t)(rowBase + aRow) * K + aCol;
    const float* Bptr = B + (size_t)bRow * N + colBase + bCol;

    float acc[8][8];
    #pragma unroll
    for (int i = 0; i < 8; i++)
        #pragma unroll
        for (int j = 0; j < 8; j++) acc[i][j] = 0.f;

    for (int k0 = 0; k0 < K; k0 += 8) {
        float4 av = *(const float4*)(Aptr + k0);
        float4 bv = *(const float4*)(Bptr + (size_t)k0 * N);
        As[aCol+0][aRow] = av.x;
        As[aCol+1][aRow] = av.y;
        As[aCol+2][aRow] = av.z;
        As[aCol+3][aRow] = av.w;
        *(float4*)&Bs[bRow][bCol] = bv;
        __syncthreads();

        #pragma unroll
        for (int kk = 0; kk < 8; kk++) {
            float a[8], b[8];
            *(float4*)&a[0] = *(const float4*)&As[kk][ty*4];
            *(float4*)&a[4] = *(const float4*)&As[kk][64 + ty*4];
            *(float4*)&b[0] = *(const float4*)&Bs[kk][tx*4];
            *(float4*)&b[4] = *(const float4*)&Bs[kk][64 + tx*4];
            #pragma unroll
            for (int i = 0; i < 8; i++)
                #pragma unroll
                for (int j = 0; j < 8; j++)
                    acc[i][j] += a[i] * b[j];
        }
        __syncthreads();
    }

    #pragma unroll
    for (int ih = 0; ih < 2; ih++)
    #pragma unroll
    for (int ii = 0; ii < 4; ii++) {
        int row = rowBase + ih*64 + ty*4 + ii;
        #pragma unroll
        for (int jh = 0; jh < 2; jh++) {
            int col = colBase + jh*64 + tx*4;
            float4 bb = *(const float4*)(bias + col);
            float4 o;
            o.x = acc[ih*4+ii][jh*4+0] + bb.x;
            o.y = acc[ih*4+ii][jh*4+1] + bb.y;
            o.z = acc[ih*4+ii][jh*4+2] + bb.z;
            o.w = acc[ih*4+ii][jh*4+3] + bb.w;
            *(float4*)(C + (size_t)row * N + col) = o;
        }
    }
}

// ---------------------------------------------------------------------------
// Attention: for each (batch,head, 64-row q-tile), stream 64-row k-tiles with
// jt >= qt (strict-triu mask => lower tiles contribute nothing).
//   ctx[q,:] = sum_{j>q} exp(-0.5 * D[q]·D[j]) * V[j,:]
// smem: DqT[d][q], DkT[d][j] (reused as S[q][j]), V[j][d] — 3 x 16KB = 48KB.
// 256 threads, 4x4 register micro-tiles.
// ---------------------------------------------------------------------------
__global__ __launch_bounds__(256) void attn_kernel() {
    __shared__ __align__(16) float sDq [64*64];  // [d][q]
    __shared__ __align__(16) float sDkS[64*64];  // [d][j] during score; [q][j] as S
    __shared__ __align__(16) float sV  [64*64];  // [j][d]

    const int tid = threadIdx.x;
    const int ty  = tid >> 4;   // 0..15 -> q rows ty*4..+3
    const int tx  = tid & 15;   // 0..15 -> cols  tx*4..+3
    const int qt  = blockIdx.x;
    const int bh  = blockIdx.y;
    const int b   = bh >> 4;
    const int h   = bh & 15;
    const int q0  = qt * 64;

    const float* Dbase = g_D + (size_t)b*SS*HH + h*HDD;  // row s stride HH
    const float* Vbase = g_V + (size_t)b*SS*HH + h*HDD;

    // cooperative tile loaders: 64 rows, 4 threads/row, 16 floats each
    const int lr = tid >> 2;          // 0..63
    const int lc = (tid & 3) * 16;    // 0,16,32,48

    // Load Dq tile transposed: sDq[d][q]
    {
        const float* src = Dbase + (size_t)(q0 + lr)*HH + lc;
        #pragma unroll
        for (int u = 0; u < 16; u += 4) {
            float4 v = *(const float4*)(src + u);
            sDq[(lc+u+0)*64 + lr] = v.x;
            sDq[(lc+u+1)*64 + lr] = v.y;
            sDq[(lc+u+2)*64 + lr] = v.z;
            sDq[(lc+u+3)*64 + lr] = v.w;
        }
    }

    float ctx[4][4];
    #pragma unroll
    for (int i = 0; i < 4; i++)
        #pragma unroll
        for (int j = 0; j < 4; j++) ctx[i][j] = 0.f;

    for (int jt = qt; jt < SS/64; jt++) {
        const int j0 = jt * 64;
        __syncthreads();  // previous iteration's readers of sDkS/sV done; sDq load fenced below
        {
            const float* srcK = Dbase + (size_t)(j0 + lr)*HH + lc;
            const float* srcV = Vbase + (size_t)(j0 + lr)*HH + lc;
            #pragma unroll
            for (int u = 0; u < 16; u += 4) {
                float4 v = *(const float4*)(srcK + u);
                sDkS[(lc+u+0)*64 + lr] = v.x;
                sDkS[(lc+u+1)*64 + lr] = v.y;
                sDkS[(lc+u+2)*64 + lr] = v.z;
                sDkS[(lc+u+3)*64 + lr] = v.w;
                *(float4*)&sV[lr*64 + lc + u] = *(const float4*)(srcV + u);
            }
        }
        __syncthreads();

        // score: sc[i][j] = D[q0+ty*4+i] · D[j0+tx*4+j]
        float sc[4][4];
        #pragma unroll
        for (int i = 0; i < 4; i++)
            #pragma unroll
            for (int j = 0; j < 4; j++) sc[i][j] = 0.f;

        #pragma unroll 8
        for (int kk = 0; kk < 64; kk++) {
            float4 a  = *(const float4*)&sDq [kk*64 + ty*4];
            float4 bv = *(const float4*)&sDkS[kk*64 + tx*4];
            sc[0][0] += a.x*bv.x; sc[0][1] += a.x*bv.y; sc[0][2] += a.x*bv.z; sc[0][3] += a.x*bv.w;
            sc[1][0] += a.y*bv.x; sc[1][1] += a.y*bv.y; sc[1][2] += a.y*bv.z; sc[1][3] += a.y*bv.w;
            sc[2][0] += a.z*bv.x; sc[2][1] += a.z*bv.y; sc[2][2] += a.z*bv.z; sc[2][3] += a.z*bv.w;
            sc[3][0] += a.w*bv.x; sc[3][1] += a.w*bv.y; sc[3][2] += a.w*bv.z; sc[3][3] += a.w*bv.w;
        }

        // mask (strictly above diagonal) + exp
        #pragma unroll
        for (int i = 0; i < 4; i++) {
            const int qg = q0 + ty*4 + i;
            #pragma unroll
            for (int j = 0; j < 4; j++) {
                const int jg = j0 + tx*4 + j;
                float w = __expf(-0.5f * sc[i][j]);
                sc[i][j] = (jg > qg) ? w : 0.f;
            }
        }

        __syncthreads();  // everyone done reading sDkS as DkT
        #pragma unroll
        for (int i = 0; i < 4; i++) {
            float4 o = make_float4(sc[i][0], sc[i][1], sc[i][2], sc[i][3]);
            *(float4*)&sDkS[(ty*4+i)*64 + tx*4] = o;   // S[q][j]
        }
        __syncthreads();

        // PV: ctx[q][d] += S[q][jj] * V[jj][d]
        #pragma unroll 8
        for (int jj = 0; jj < 64; jj++) {
            float4 vv = *(const float4*)&sV[jj*64 + tx*4];
            float s0 = sDkS[(ty*4+0)*64 + jj];
            float s1 = sDkS[(ty*4+1)*64 + jj];
            float s2 = sDkS[(ty*4+2)*64 + jj];
            float s3 = sDkS[(ty*4+3)*64 + jj];
            ctx[0][0] += s0*vv.x; ctx[0][1] += s0*vv.y; ctx[0][2] += s0*vv.z; ctx[0][3] += s0*vv.w;
            ctx[1][0] += s1*vv.x; ctx[1][1] += s1*vv.y; ctx[1][2] += s1*vv.z; ctx[1][3] += s1*vv.w;
            ctx[2][0] += s2*vv.x; ctx[2][1] += s2*vv.y; ctx[2][2] += s2*vv.z; ctx[2][3] += s2*vv.w;
            ctx[3][0] += s3*vv.x; ctx[3][1] += s3*vv.y; ctx[3][2] += s3*vv.z; ctx[3][3] += s3*vv.w;
        }
    }

    // write context back in merged [B,S,H] layout (head-interleaved)
    float* Cb = g_C + (size_t)b*SS*HH + h*HDD;
    #pragma unroll
    for (int i = 0; i < 4; i++) {
        float4 o = make_float4(ctx[i][0], ctx[i][1], ctx[i][2], ctx[i][3]);
        *(float4*)(Cb + (size_t)(q0 + ty*4 + i)*HH + tx*4) = o;
    }
}

// ---------------------------------------------------------------------------
extern "C" void kernel_launch(void* const* d_in, const int* in_sizes, int n_in,
                              void* d_out, int out_size) {
    const float* x  = (const float*)d_in[0];
    const float* Wq = (const float*)d_in[1];
    const float* bq = (const float*)d_in[2];
    const float* Wk = (const float*)d_in[3];
    const float* bk = (const float*)d_in[4];
    const float* Wv = (const float*)d_in[5];
    const float* bv = (const float*)d_in[6];
    const float* Wo = (const float*)d_in[7];
    const float* bo = (const float*)d_in[8];
    float* out = (float*)d_out;

    float *pWd, *pbd, *pD, *pV, *pC;
    cudaGetSymbolAddress((void**)&pWd, g_Wd);
    cudaGetSymbolAddress((void**)&pbd, g_bd);
    cudaGetSymbolAddress((void**)&pD,  g_D);
    cudaGetSymbolAddress((void**)&pV,  g_V);
    cudaGetSymbolAddress((void**)&pC,  g_C);

    prep_kernel<<<(HH*HH + 255)/256, 256>>>(Wq, Wk, bq, bk);

    dim3 gg(HH/128, MT/128);  // (8, 32)
    sgemm_bias<<<gg, 256>>>(x, pWd, pbd, pD, MT, HH, HH);   // D = x@(Wq-Wk)+(bq-bk)
    sgemm_bias<<<gg, 256>>>(x, Wv,  bv,  pV, MT, HH, HH);   // V = x@Wv+bv

    attn_kernel<<<dim3(SS/64, BB*NHH), 256>>>();            // C = (mask*exp(-0.5 DDᵀ)) @ V

    sgemm_bias<<<gg, 256>>>(pC, Wo, bo, out, MT, HH, HH);   // out = C@Wo+bo
}

// round 2
// speedup vs baseline: 1.1719x; 1.1719x over previous
#include <cuda_runtime.h>
#include <cstdint>

// Problem constants (fixed shapes per reference)
#define HH  1024
#define BB  2
#define SS  2048
#define NHH 16
#define HDD 64
#define MT  (BB*SS)   // 4096 total rows
#define PADS 72       // smem row stride (words) for attention tiles

// Scratch (static device globals — allocation-free per harness rules)
__device__ float g_Wd[HH*HH];
__device__ float g_bd[HH];
__device__ float g_D[MT*HH];   // D = x@(Wq-Wk)+(bq-bk), layout [B,S,H]
__device__ float g_V[MT*HH];   // V = x@Wv+bv,           layout [B,S,H]
__device__ float g_C[MT*HH];   // attention context,     layout [B,S,H]

// ---------------------------------------------------------------------------
// Prep: Wd = Wq - Wk, bd = bq - bk
// ---------------------------------------------------------------------------
__global__ void prep_kernel(const float* __restrict__ Wq, const float* __restrict__ Wk,
                            const float* __restrict__ bq, const float* __restrict__ bk) {
    int i = blockIdx.x * blockDim.x + threadIdx.x;
    if (i < HH*HH) g_Wd[i] = Wq[i] - Wk[i];
    if (i < HH)    g_bd[i] = bq[i] - bk[i];
}

// ---------------------------------------------------------------------------
// SGEMM: C[M,N] = A[M,K] @ B[K,N] + bias[N]   (fp32 SIMT, unchanged)
// ---------------------------------------------------------------------------
__global__ __launch_bounds__(256) void sgemm_bias(
    const float* __restrict__ A, const float* __restrict__ B,
    const float* __restrict__ bias, float* __restrict__ C,
    int M, int N, int K)
{
    __shared__ __align__(16) float As[8][128];   // [k][m] (transposed)
    __shared__ __align__(16) float Bs[8][128];   // [k][n]

    const int tid = threadIdx.x;
    const int ty  = tid >> 4;
    const int tx  = tid & 15;
    const int rowBase = blockIdx.y * 128;
    const int colBase = blockIdx.x * 128;

    const int aRow = tid >> 1;
    const int aCol = (tid & 1) * 4;
    const int bRow = tid >> 5;
    const int bCol = (tid & 31) * 4;

    const float* Aptr = A + (size_t)(rowBase + aRow) * K + aCol;
    const float* Bptr = B + (size_t)bRow * N + colBase + bCol;

    float acc[8][8];
    #pragma unroll
    for (int i = 0; i < 8; i++)
        #pragma unroll
        for (int j = 0; j < 8; j++) acc[i][j] = 0.f;

    for (int k0 = 0; k0 < K; k0 += 8) {
        float4 av = *(const float4*)(Aptr + k0);
        float4 bv = *(const float4*)(Bptr + (size_t)k0 * N);
        As[aCol+0][aRow] = av.x;
        As[aCol+1][aRow] = av.y;
        As[aCol+2][aRow] = av.z;
        As[aCol+3][aRow] = av.w;
        *(float4*)&Bs[bRow][bCol] = bv;
        __syncthreads();

        #pragma unroll
        for (int kk = 0; kk < 8; kk++) {
            float a[8], b[8];
            *(float4*)&a[0] = *(const float4*)&As[kk][ty*4];
            *(float4*)&a[4] = *(const float4*)&As[kk][64 + ty*4];
            *(float4*)&b[0] = *(const float4*)&Bs[kk][tx*4];
            *(float4*)&b[4] = *(const float4*)&Bs[kk][64 + tx*4];
            #pragma unroll
            for (int i = 0; i < 8; i++)
                #pragma unroll
                for (int j = 0; j < 8; j++)
                    acc[i][j] += a[i] * b[j];
        }
        __syncthreads();
    }

    #pragma unroll
    for (int ih = 0; ih < 2; ih++)
    #pragma unroll
    for (int ii = 0; ii < 4; ii++) {
        int row = rowBase + ih*64 + ty*4 + ii;
        #pragma unroll
        for (int jh = 0; jh < 2; jh++) {
            int col = colBase + jh*64 + tx*4;
            float4 bb = *(const float4*)(bias + col);
            float4 o;
            o.x = acc[ih*4+ii][jh*4+0] + bb.x;
            o.y = acc[ih*4+ii][jh*4+1] + bb.y;
            o.z = acc[ih*4+ii][jh*4+2] + bb.z;
            o.w = acc[ih*4+ii][jh*4+3] + bb.w;
            *(float4*)(C + (size_t)row * N + col) = o;
        }
    }
}

// ---------------------------------------------------------------------------
// mma.sync tf32 helpers
// ---------------------------------------------------------------------------
__device__ __forceinline__ uint32_t f2tf(float x) {
    uint32_t r;
    asm("cvt.rna.tf32.f32 %0, %1;" : "=r"(r) : "f"(x));
    return r;
}
__device__ __forceinline__ void mma_tf32(float* d,
    uint32_t a0, uint32_t a1, uint32_t a2, uint32_t a3,
    uint32_t b0, uint32_t b1)
{
    asm volatile(
        "mma.sync.aligned.m16n8k8.row.col.f32.tf32.tf32.f32 "
        "{%0,%1,%2,%3},{%4,%5,%6,%7},{%8,%9},{%0,%1,%2,%3};"
        : "+f"(d[0]), "+f"(d[1]), "+f"(d[2]), "+f"(d[3])
        : "r"(a0), "r"(a1), "r"(a2), "r"(a3), "r"(b0), "r"(b1));
}

// ---------------------------------------------------------------------------
// Attention with tensor cores (mma.sync tf32).
// Per (b,h,64-row q-tile): stream 64-row j-tiles (jt >= qt; strict triu mask).
//   score = Dq @ Dk^T  via tf32x2 split (3 mmas)  -> mask+exp -> S (smem)
//   ctx  += S @ V      via plain tf32
// 8 warps: warp w owns rows (w&3)*16, cols (w>>2)*32 of the 64x64 tiles.
// Dyn smem: 3 x 64 x 72 floats = 55296 B.
// ---------------------------------------------------------------------------
__global__ __launch_bounds__(256) void attn_mma() {
    extern __shared__ float sm[];
    float* sDq  = sm;                // [64][PADS]  Dq tile (row-major q,d)
    float* sDkS = sm + 64*PADS;      // Dk tile, reused as S[q][j]
    float* sV   = sm + 2*64*PADS;    // V tile (row-major j,d)

    const int tid  = threadIdx.x;
    const int w    = tid >> 5;
    const int lane = tid & 31;
    const int g    = lane >> 2;     // 0..7
    const int t    = lane & 3;      // 0..3
    const int mrow  = (w & 3) * 16; // warp row block within 64
    const int nhalf = (w >> 2) * 32;// warp col block within 64

    const int qt = blockIdx.x;
    const int bh = blockIdx.y;
    const int b  = bh >> 4;
    const int h  = bh & 15;
    const int q0 = qt * 64;

    const float* Dbase = g_D + (size_t)b*SS*HH + h*HDD;
    const float* Vbase = g_V + (size_t)b*SS*HH + h*HDD;

    // cooperative loader mapping: 64 rows, 4 threads/row, 16 floats each
    const int lr = tid >> 2;
    const int lc = (tid & 3) * 16;

    // load Dq tile (row-major, no transpose)
    {
        const float* src = Dbase + (size_t)(q0 + lr)*HH + lc;
        #pragma unroll
        for (int u = 0; u < 16; u += 4)
            *(float4*)&sDq[lr*PADS + lc + u] = *(const float4*)(src + u);
    }

    float oacc[4][4];
    #pragma unroll
    for (int i = 0; i < 4; i++)
        #pragma unroll
        for (int j = 0; j < 4; j++) oacc[i][j] = 0.f;

    for (int jt = qt; jt < SS/64; jt++) {
        const int j0 = jt * 64;
        __syncthreads();   // prev iter readers done (also fences Dq load, iter 0)
        {
            const float* srcK = Dbase + (size_t)(j0 + lr)*HH + lc;
            const float* srcV = Vbase + (size_t)(j0 + lr)*HH + lc;
            #pragma unroll
            for (int u = 0; u < 16; u += 4) {
                *(float4*)&sDkS[lr*PADS + lc + u] = *(const float4*)(srcK + u);
                *(float4*)&sV  [lr*PADS + lc + u] = *(const float4*)(srcV + u);
            }
        }
        __syncthreads();

        // ---- score phase: sacc = Dq @ Dk^T (tf32x2: hi*hi + hi*lo + lo*hi)
        float sacc[4][4];
        #pragma unroll
        for (int i = 0; i < 4; i++)
            #pragma unroll
            for (int j = 0; j < 4; j++) sacc[i][j] = 0.f;

        #pragma unroll
        for (int k0 = 0; k0 < 64; k0 += 8) {
            float a0f = sDq[(mrow+g  )*PADS + k0 + t];
            float a1f = sDq[(mrow+g+8)*PADS + k0 + t];
            float a2f = sDq[(mrow+g  )*PADS + k0 + t + 4];
            float a3f = sDq[(mrow+g+8)*PADS + k0 + t + 4];
            uint32_t ah0 = f2tf(a0f), ah1 = f2tf(a1f), ah2 = f2tf(a2f), ah3 = f2tf(a3f);
            uint32_t al0 = f2tf(a0f - __uint_as_float(ah0));
            uint32_t al1 = f2tf(a1f - __uint_as_float(ah1));
            uint32_t al2 = f2tf(a2f - __uint_as_float(ah2));
            uint32_t al3 = f2tf(a3f - __uint_as_float(ah3));

            #pragma unroll
            for (int nt = 0; nt < 4; nt++) {
                const int jb = nhalf + nt*8;
                float b0f = sDkS[(jb+g)*PADS + k0 + t];      // Dk[j=jb+g][d=k0+t]
                float b1f = sDkS[(jb+g)*PADS + k0 + t + 4];
                uint32_t bh0 = f2tf(b0f), bh1 = f2tf(b1f);
                uint32_t bl0 = f2tf(b0f - __uint_as_float(bh0));
                uint32_t bl1 = f2tf(b1f - __uint_as_float(bh1));
                mma_tf32(sacc[nt], ah0, ah1, ah2, ah3, bh0, bh1);
                mma_tf32(sacc[nt], ah0, ah1, ah2, ah3, bl0, bl1);
                mma_tf32(sacc[nt], al0, al1, al2, al3, bh0, bh1);
            }
        }

        // ---- mask (strictly above diagonal) + exp
        const int r0 = q0 + mrow + g;
        #pragma unroll
        for (int nt = 0; nt < 4; nt++) {
            const int colb = j0 + nhalf + nt*8 + 2*t;
            sacc[nt][0] = (colb     > r0    ) ? __expf(-0.5f * sacc[nt][0]) : 0.f;
            sacc[nt][1] = (colb + 1 > r0    ) ? __expf(-0.5f * sacc[nt][1]) : 0.f;
            sacc[nt][2] = (colb     > r0 + 8) ? __expf(-0.5f * sacc[nt][2]) : 0.f;
            sacc[nt][3] = (colb + 1 > r0 + 8) ? __expf(-0.5f * sacc[nt][3]) : 0.f;
        }

        __syncthreads();   // all warps done reading Dk tile
        #pragma unroll
        for (int nt = 0; nt < 4; nt++) {
            const int cb = nhalf + nt*8 + 2*t;
            *(float2*)&sDkS[(mrow+g  )*PADS + cb] = make_float2(sacc[nt][0], sacc[nt][1]);
            *(float2*)&sDkS[(mrow+g+8)*PADS + cb] = make_float2(sacc[nt][2], sacc[nt][3]);
        }
        __syncthreads();

        // ---- PV phase: oacc += S @ V  (plain tf32)
        #pragma unroll
        for (int k0 = 0; k0 < 64; k0 += 8) {
            uint32_t a0 = f2tf(sDkS[(mrow+g  )*PADS + k0 + t]);
            uint32_t a1 = f2tf(sDkS[(mrow+g+8)*PADS + k0 + t]);
            uint32_t a2 = f2tf(sDkS[(mrow+g  )*PADS + k0 + t + 4]);
            uint32_t a3 = f2tf(sDkS[(mrow+g+8)*PADS + k0 + t + 4]);
            #pragma unroll
            for (int nt = 0; nt < 4; nt++) {
                const int dbc = nhalf + nt*8;
                uint32_t b0 = f2tf(sV[(k0+t  )*PADS + dbc + g]);   // V[j=k0+t][d=dbc+g]
                uint32_t b1 = f2tf(sV[(k0+t+4)*PADS + dbc + g]);
                mma_tf32(oacc[nt], a0, a1, a2, a3, b0, b1);
            }
        }
    }

    // write ctx back in merged [B,S,H] layout (head-interleaved)
    float* Cb = g_C + (size_t)b*SS*HH + h*HDD;
    #pragma unroll
    for (int nt = 0; nt < 4; nt++) {
        const int col = nhalf + nt*8 + 2*t;
        *(float2*)(Cb + (size_t)(q0 + mrow + g    )*HH + col) = make_float2(oacc[nt][0], oacc[nt][1]);
        *(float2*)(Cb + (size_t)(q0 + mrow + g + 8)*HH + col) = make_float2(oacc[nt][2], oacc[nt][3]);
    }
}

// ---------------------------------------------------------------------------
extern "C" void kernel_launch(void* const* d_in, const int* in_sizes, int n_in,
                              void* d_out, int out_size) {
    const float* x  = (const float*)d_in[0];
    const float* Wq = (const float*)d_in[1];
    const float* bq = (const float*)d_in[2];
    const float* Wk = (const float*)d_in[3];
    const float* bk = (const float*)d_in[4];
    const float* Wv = (const float*)d_in[5];
    const float* bv = (const float*)d_in[6];
    const float* Wo = (const float*)d_in[7];
    const float* bo = (const float*)d_in[8];
    float* out = (float*)d_out;

    float *pWd, *pbd, *pD, *pV, *pC;
    cudaGetSymbolAddress((void**)&pWd, g_Wd);
    cudaGetSymbolAddress((void**)&pbd, g_bd);
    cudaGetSymbolAddress((void**)&pD,  g_D);
    cudaGetSymbolAddress((void**)&pV,  g_V);
    cudaGetSymbolAddress((void**)&pC,  g_C);

    prep_kernel<<<(HH*HH + 255)/256, 256>>>(Wq, Wk, bq, bk);

    dim3 gg(HH/128, MT/128);  // (8, 32)
    sgemm_bias<<<gg, 256>>>(x, pWd, pbd, pD, MT, HH, HH);   // D = x@(Wq-Wk)+(bq-bk)
    sgemm_bias<<<gg, 256>>>(x, Wv,  bv,  pV, MT, HH, HH);   // V = x@Wv+bv

    const int smem_bytes = 3 * 64 * PADS * sizeof(float);   // 55296
    static bool attr_set = false;
    if (!attr_set) {
        cudaFuncSetAttribute(attn_mma, cudaFuncAttributeMaxDynamicSharedMemorySize, smem_bytes);
        attr_set = true;
    }
    attn_mma<<<dim3(SS/64, BB*NHH), 256, smem_bytes>>>();   // C = (mask*exp(-0.5 DDᵀ)) @ V

    sgemm_bias<<<gg, 256>>>(pC, Wo, bo, out, MT, HH, HH);   // out = C@Wo+bo
}

// round 3
// speedup vs baseline: 1.7212x; 1.4687x over previous
#include <cuda_runtime.h>
#include <cstdint>

#define HH  1024
#define BB  2
#define SS  2048
#define NHH 16
#define HDD 64
#define MT  (BB*SS)   // 4096

// ---------------- scratch globals (allocation-free) ----------------
__device__ __align__(128) float g_xhi[MT*HH];
__device__ __align__(128) float g_xlo[MT*HH];
__device__ __align__(128) float g_WdThi[HH*HH];   // (Wq-Wk)^T hi, tf32-rounded
__device__ __align__(128) float g_WdTlo[HH*HH];
__device__ __align__(128) float g_WvT[HH*HH];     // Wv^T tf32-rounded
__device__ __align__(128) float g_WoT[HH*HH];     // Wo^T tf32-rounded
__device__ __align__(128) float g_bd[HH];
__device__ __align__(128) float g_Dhi[MT*HH];     // tf32(D)
__device__ __align__(128) float g_Dlo[MT*HH];     // tf32(D - tf32(D))
__device__ __align__(128) float g_V[MT*HH];       // tf32-rounded V (bias incl.)
__device__ __align__(128) float g_C[MT*HH];       // tf32-rounded attention ctx

// ---------------- helpers ----------------
__device__ __forceinline__ float tfr(float x) {   // round fp32 -> tf32 (bits stay fp32-valid)
    uint32_t r;
    asm("cvt.rna.tf32.f32 %0, %1;" : "=r"(r) : "f"(x));
    return __uint_as_float(r);
}
__device__ __forceinline__ void cp16(float* s, const float* g) {
    uint32_t sa = (uint32_t)__cvta_generic_to_shared(s);
    asm volatile("cp.async.cg.shared.global [%0], [%1], 16;" :: "r"(sa), "l"(g));
}
__device__ __forceinline__ void cp_commit() { asm volatile("cp.async.commit_group;"); }
template<int N> __device__ __forceinline__ void cp_wait() {
    asm volatile("cp.async.wait_group %0;" :: "n"(N));
}
__device__ __forceinline__ void mma8(float* d, const uint32_t* a, uint32_t b0, uint32_t b1) {
    asm volatile(
        "mma.sync.aligned.m16n8k8.row.col.f32.tf32.tf32.f32 "
        "{%0,%1,%2,%3},{%4,%5,%6,%7},{%8,%9},{%0,%1,%2,%3};"
        : "+f"(d[0]), "+f"(d[1]), "+f"(d[2]), "+f"(d[3])
        : "r"(a[0]), "r"(a[1]), "r"(a[2]), "r"(a[3]), "r"(b0), "r"(b1));
}

// ---------------- prep: x -> hi/lo planes; bd = bq-bk ----------------
__global__ void prep_x(const float* __restrict__ x,
                       const float* __restrict__ bq, const float* __restrict__ bk) {
    int i = blockIdx.x * 256 + threadIdx.x;
    float v = x[i];
    float hi = tfr(v);
    g_xhi[i] = hi;
    g_xlo[i] = tfr(v - hi);
    if (i < HH) g_bd[i] = bq[i] - bk[i];
}

// ---------------- prep: transpose + tf32-convert weights ----------------
__global__ void prep_w(const float* __restrict__ Wq, const float* __restrict__ Wk,
                       const float* __restrict__ Wv, const float* __restrict__ Wo) {
    __shared__ float t0[32][33];
    __shared__ float t1[32][33];
    const int z = blockIdx.z;
    const int c0 = blockIdx.x * 32, r0 = blockIdx.y * 32;
    const int tx = threadIdx.x & 31, ty = threadIdx.x >> 5;   // ty 0..7
    #pragma unroll
    for (int rr = ty; rr < 32; rr += 8) {
        int idx = (r0 + rr) * HH + c0 + tx;
        if (z == 0) {
            float v = Wq[idx] - Wk[idx];
            float hi = tfr(v);
            t0[rr][tx] = hi;
            t1[rr][tx] = tfr(v - hi);
        } else if (z == 1) t0[rr][tx] = tfr(Wv[idx]);
        else               t0[rr][tx] = tfr(Wo[idx]);
    }
    __syncthreads();
    #pragma unroll
    for (int rr = ty; rr < 32; rr += 8) {
        int odx = (c0 + rr) * HH + r0 + tx;   // transposed
        if (z == 0) { g_WdThi[odx] = t0[tx][rr]; g_WdTlo[odx] = t1[tx][rr]; }
        else if (z == 1) g_WvT[odx] = t0[tx][rr];
        else             g_WoT[odx] = t0[tx][rr];
    }
}

// ---------------- tf32 GEMM (plain): C = A @ BT^T + bias ----------------
// A[M,K] tf32-rounded floats, BT[N,K] tf32-rounded. 128x128 tile, BK=8,
// 3-stage cp.async, 8 warps (4m x 2n), warp tile 32x64.
#define GP 12
template<bool ROUND>
__global__ __launch_bounds__(256, 2) void gemm_plain(
    const float* __restrict__ A, const float* __restrict__ BT,
    const float* __restrict__ bias, float* __restrict__ C)
{
    extern __shared__ float sm[];
    const int K = HH, N = HH;
    const int tid = threadIdx.x, w = tid >> 5, lane = tid & 31;
    const int g = lane >> 2, t = lane & 3;
    const int wm = (w & 3) * 32, wn = (w >> 2) * 64;
    const int rowBase = blockIdx.y * 128, colBase = blockIdx.x * 128;
    const int lr = tid >> 1, lc = (tid & 1) * 4;

    const float* pA = A  + (size_t)(rowBase + lr) * K + lc;
    const float* pB = BT + (size_t)(colBase + lr) * K + lc;

    float acc[2][8][4];
    #pragma unroll
    for (int mt = 0; mt < 2; mt++)
        #pragma unroll
        for (int nt = 0; nt < 8; nt++)
            #pragma unroll
            for (int q = 0; q < 4; q++) acc[mt][nt][q] = 0.f;

    const int NIT = K / 8;  // 128
    const int off = lr * GP + lc;
    auto issue = [&](int it, int s) {
        float* base = sm + s * 2 * 128 * GP;
        cp16(base + off,            pA + it * 8);
        cp16(base + 128*GP + off,   pB + it * 8);
    };
    issue(0, 0); cp_commit();
    issue(1, 1); cp_commit();

    for (int i = 0; i < NIT; i++) {
        cp_wait<1>();
        __syncthreads();
        const float* base = sm + (i % 3) * 2 * 128 * GP;
        const float* sA = base;
        const float* sB = base + 128 * GP;
        uint32_t a[2][4];
        #pragma unroll
        for (int mt = 0; mt < 2; mt++) {
            int r = wm + mt * 16 + g;
            a[mt][0] = __float_as_uint(sA[r * GP + t]);
            a[mt][1] = __float_as_uint(sA[(r + 8) * GP + t]);
            a[mt][2] = __float_as_uint(sA[r * GP + t + 4]);
            a[mt][3] = __float_as_uint(sA[(r + 8) * GP + t + 4]);
        }
        #pragma unroll
        for (int nt = 0; nt < 8; nt++) {
            int c = wn + nt * 8 + g;
            uint32_t b0 = __float_as_uint(sB[c * GP + t]);
            uint32_t b1 = __float_as_uint(sB[c * GP + t + 4]);
            mma8(acc[0][nt], a[0], b0, b1);
            mma8(acc[1][nt], a[1], b0, b1);
        }
        if (i + 2 < NIT) issue(i + 2, (i + 2) % 3);
        cp_commit();
    }

    #pragma unroll
    for (int mt = 0; mt < 2; mt++)
        #pragma unroll
        for (int nt = 0; nt < 8; nt++) {
            int row = rowBase + wm + mt * 16 + g;
            int col = colBase + wn + nt * 8 + 2 * t;
            float2 bb = *(const float2*)(bias + col);
            float v00 = acc[mt][nt][0] + bb.x, v01 = acc[mt][nt][1] + bb.y;
            float v10 = acc[mt][nt][2] + bb.x, v11 = acc[mt][nt][3] + bb.y;
            if (ROUND) { v00 = tfr(v00); v01 = tfr(v01); v10 = tfr(v10); v11 = tfr(v11); }
            *(float2*)(C + (size_t)row * N + col)       = make_float2(v00, v01);
            *(float2*)(C + (size_t)(row + 8) * N + col) = make_float2(v10, v11);
        }
}

// ---------------- tf32x2 split GEMM for D; writes hi/lo planes ----------------
__global__ __launch_bounds__(256, 2) void gemm_split(
    const float* __restrict__ Ah, const float* __restrict__ Al,
    const float* __restrict__ Bh, const float* __restrict__ Bl,
    const float* __restrict__ bias,
    float* __restrict__ Chi, float* __restrict__ Clo)
{
    extern __shared__ float sm[];
    const int K = HH, N = HH;
    const int tid = threadIdx.x, w = tid >> 5, lane = tid & 31;
    const int g = lane >> 2, t = lane & 3;
    const int wm = (w & 3) * 32, wn = (w >> 2) * 64;
    const int rowBase = blockIdx.y * 128, colBase = blockIdx.x * 128;
    const int lr = tid >> 1, lc = (tid & 1) * 4;

    const float* pAh = Ah + (size_t)(rowBase + lr) * K + lc;
    const float* pAl = Al + (size_t)(rowBase + lr) * K + lc;
    const float* pBh = Bh + (size_t)(colBase + lr) * K + lc;
    const float* pBl = Bl + (size_t)(colBase + lr) * K + lc;

    float acc[2][8][4];
    #pragma unroll
    for (int mt = 0; mt < 2; mt++)
        #pragma unroll
        for (int nt = 0; nt < 8; nt++)
            #pragma unroll
            for (int q = 0; q < 4; q++) acc[mt][nt][q] = 0.f;

    const int NIT = K / 8;
    const int off = lr * GP + lc;
    auto issue = [&](int it, int s) {
        float* base = sm + s * 4 * 128 * GP;
        cp16(base + off,              pAh + it * 8);
        cp16(base + 128*GP   + off,   pAl + it * 8);
        cp16(base + 2*128*GP + off,   pBh + it * 8);
        cp16(base + 3*128*GP + off,   pBl + it * 8);
    };
    issue(0, 0); cp_commit();
    issue(1, 1); cp_commit();

    for (int i = 0; i < NIT; i++) {
        cp_wait<1>();
        __syncthreads();
        const float* base = sm + (i % 3) * 4 * 128 * GP;
        const float* sAh = base;
        const float* sAl = base + 128 * GP;
        const float* sBh = base + 2 * 128 * GP;
        const float* sBl = base + 3 * 128 * GP;
        uint32_t ah[2][4], al[2][4];
        #pragma unroll
        for (int mt = 0; mt < 2; mt++) {
            int r = wm + mt * 16 + g;
            ah[mt][0] = __float_as_uint(sAh[r * GP + t]);
            ah[mt][1] = __float_as_uint(sAh[(r + 8) * GP + t]);
            ah[mt][2] = __float_as_uint(sAh[r * GP + t + 4]);
            ah[mt][3] = __float_as_uint(sAh[(r + 8) * GP + t + 4]);
            al[mt][0] = __float_as_uint(sAl[r * GP + t]);
            al[mt][1] = __float_as_uint(sAl[(r + 8) * GP + t]);
            al[mt][2] = __float_as_uint(sAl[r * GP + t + 4]);
            al[mt][3] = __float_as_uint(sAl[(r + 8) * GP + t + 4]);
        }
        #pragma unroll
        for (int nt = 0; nt < 8; nt++) {
            int c = wn + nt * 8 + g;
            uint32_t bh0 = __float_as_uint(sBh[c * GP + t]);
            uint32_t bh1 = __float_as_uint(sBh[c * GP + t + 4]);
            uint32_t bl0 = __float_as_uint(sBl[c * GP + t]);
            uint32_t bl1 = __float_as_uint(sBl[c * GP + t + 4]);
            #pragma unroll
            for (int mt = 0; mt < 2; mt++) {
                mma8(acc[mt][nt], ah[mt], bh0, bh1);
                mma8(acc[mt][nt], ah[mt], bl0, bl1);
                mma8(acc[mt][nt], al[mt], bh0, bh1);
            }
        }
        if (i + 2 < NIT) issue(i + 2, (i + 2) % 3);
        cp_commit();
    }

    #pragma unroll
    for (int mt = 0; mt < 2; mt++)
        #pragma unroll
        for (int nt = 0; nt < 8; nt++) {
            int row = rowBase + wm + mt * 16 + g;
            int col = colBase + wn + nt * 8 + 2 * t;
            float2 bb = *(const float2*)(bias + col);
            float v00 = acc[mt][nt][0] + bb.x, v01 = acc[mt][nt][1] + bb.y;
            float v10 = acc[mt][nt][2] + bb.x, v11 = acc[mt][nt][3] + bb.y;
            float h00 = tfr(v00), h01 = tfr(v01), h10 = tfr(v10), h11 = tfr(v11);
            *(float2*)(Chi + (size_t)row * N + col)       = make_float2(h00, h01);
            *(float2*)(Chi + (size_t)(row + 8) * N + col) = make_float2(h10, h11);
            *(float2*)(Clo + (size_t)row * N + col)       = make_float2(tfr(v00 - h00), tfr(v01 - h01));
            *(float2*)(Clo + (size_t)(row + 8) * N + col) = make_float2(tfr(v10 - h10), tfr(v11 - h11));
        }
}

// ---------------- attention (tensor-core, pre-split operands) ----------------
// Per (b,h,64-q-tile): stream j-tiles jt>=qt, 2-stage cp.async double buffer.
// score = Dq@Dk^T via 3-mma tf32x2 (hi/lo preloaded); exp+mask; PV plain tf32.
#define PK 68
#define PPV 72
#define ASTG (64*PK*2 + 64*PPV)    // floats per stage: 13312
__global__ __launch_bounds__(256, 2) void attn_mma() {
    extern __shared__ float sm[];
    const int tid = threadIdx.x, w = tid >> 5, lane = tid & 31;
    const int g = lane >> 2, t = lane & 3;
    const int mrow = (w & 3) * 16, nhalf = (w >> 2) * 32;
    const int qt = blockIdx.x, bh = blockIdx.y;
    const int b = bh >> 4, h = bh & 15, q0 = qt * 64;

    const size_t base = (size_t)b * SS * HH + h * HDD;
    const float* Dh = g_Dhi + base;
    const float* Dl = g_Dlo + base;
    const float* Vp = g_V + base;

    // Dq fragments (hi/lo) resident in registers for the whole j-loop
    uint32_t qhi[8][4], qlo[8][4];
    {
        const size_t r0g = (size_t)(q0 + mrow + g) * HH;
        const size_t r1g = (size_t)(q0 + mrow + g + 8) * HH;
        #pragma unroll
        for (int c = 0; c < 8; c++) {
            int k = c * 8;
            qhi[c][0] = __float_as_uint(Dh[r0g + k + t]);
            qhi[c][1] = __float_as_uint(Dh[r1g + k + t]);
            qhi[c][2] = __float_as_uint(Dh[r0g + k + t + 4]);
            qhi[c][3] = __float_as_uint(Dh[r1g + k + t + 4]);
            qlo[c][0] = __float_as_uint(Dl[r0g + k + t]);
            qlo[c][1] = __float_as_uint(Dl[r1g + k + t]);
            qlo[c][2] = __float_as_uint(Dl[r0g + k + t + 4]);
            qlo[c][3] = __float_as_uint(Dl[r1g + k + t + 4]);
        }
    }

    float oacc[4][4];
    #pragma unroll
    for (int i = 0; i < 4; i++)
        #pragma unroll
        for (int j = 0; j < 4; j++) oacc[i][j] = 0.f;

    const int lr = tid >> 2, lc = (tid & 3) * 16;
    auto issue = [&](int jt, int s) {
        float* st = sm + s * ASTG;
        const float* srcH = Dh + (size_t)(jt * 64 + lr) * HH + lc;
        const float* srcL = Dl + (size_t)(jt * 64 + lr) * HH + lc;
        const float* srcV = Vp + (size_t)(jt * 64 + lr) * HH + lc;
        #pragma unroll
        for (int u = 0; u < 16; u += 4) {
            cp16(st + lr * PK + lc + u,             srcH + u);
            cp16(st + 64*PK + lr * PK + lc + u,     srcL + u);
            cp16(st + 2*64*PK + lr * PPV + lc + u,  srcV + u);
        }
    };

    int buf = 0;
    issue(qt, 0); cp_commit();
    for (int jt = qt; jt < SS / 64; jt++) {
        if (jt + 1 < SS / 64) { issue(jt + 1, buf ^ 1); cp_commit(); cp_wait<1>(); }
        else cp_wait<0>();
        __syncthreads();
        float* st = sm + buf * ASTG;
        float* sKh = st;                       // reused as S after score
        const float* sKl = st + 64 * PK;
        const float* sV  = st + 2 * 64 * PK;
        const int j0 = jt * 64;

        // score
        float sacc[4][4];
        #pragma unroll
        for (int i = 0; i < 4; i++)
            #pragma unroll
            for (int j = 0; j < 4; j++) sacc[i][j] = 0.f;

        #pragma unroll
        for (int c = 0; c < 8; c++) {
            int k = c * 8;
            #pragma unroll
            for (int nt = 0; nt < 4; nt++) {
                int jb = (nhalf + nt * 8 + g) * PK;
                uint32_t bh0 = __float_as_uint(sKh[jb + k + t]);
                uint32_t bh1 = __float_as_uint(sKh[jb + k + t + 4]);
                uint32_t bl0 = __float_as_uint(sKl[jb + k + t]);
                uint32_t bl1 = __float_as_uint(sKl[jb + k + t + 4]);
                mma8(sacc[nt], qhi[c], bh0, bh1);
                mma8(sacc[nt], qhi[c], bl0, bl1);
                mma8(sacc[nt], qlo[c], bh0, bh1);
            }
        }

        // mask (strict upper) + exp + pre-round for PV
        const int r0 = q0 + mrow + g;
        #pragma unroll
        for (int nt = 0; nt < 4; nt++) {
            int colb = j0 + nhalf + nt * 8 + 2 * t;
            sacc[nt][0] = (colb     > r0    ) ? tfr(__expf(-0.5f * sacc[nt][0])) : 0.f;
            sacc[nt][1] = (colb + 1 > r0    ) ? tfr(__expf(-0.5f * sacc[nt][1])) : 0.f;
            sacc[nt][2] = (colb     > r0 + 8) ? tfr(__expf(-0.5f * sacc[nt][2])) : 0.f;
            sacc[nt][3] = (colb + 1 > r0 + 8) ? tfr(__expf(-0.5f * sacc[nt][3])) : 0.f;
        }

        __syncthreads();   // all score reads of sKh/sKl done
        #pragma unroll
        for (int nt = 0; nt < 4; nt++) {
            int cb = nhalf + nt * 8 + 2 * t;
            *(float2*)&sKh[(mrow + g) * PK + cb]     = make_float2(sacc[nt][0], sacc[nt][1]);
            *(float2*)&sKh[(mrow + g + 8) * PK + cb] = make_float2(sacc[nt][2], sacc[nt][3]);
        }
        __syncthreads();

        // PV: oacc += S @ V
        #pragma unroll
        for (int c = 0; c < 8; c++) {
            int k = c * 8;
            uint32_t a[4];
            a[0] = __float_as_uint(sKh[(mrow + g) * PK + k + t]);
            a[1] = __float_as_uint(sKh[(mrow + g + 8) * PK + k + t]);
            a[2] = __float_as_uint(sKh[(mrow + g) * PK + k + t + 4]);
            a[3] = __float_as_uint(sKh[(mrow + g + 8) * PK + k + t + 4]);
            #pragma unroll
            for (int nt = 0; nt < 4; nt++) {
                int dbc = nhalf + nt * 8;
                uint32_t b0 = __float_as_uint(sV[(k + t) * PPV + dbc + g]);
                uint32_t b1 = __float_as_uint(sV[(k + t + 4) * PPV + dbc + g]);
                mma8(oacc[nt], a, b0, b1);
            }
        }
        __syncthreads();   // protect buf before next iter's cp targets it
        buf ^= 1;
    }

    // write ctx pre-rounded (O GEMM consumes tf32 directly)
    float* Cb = g_C + base;
    #pragma unroll
    for (int nt = 0; nt < 4; nt++) {
        int col = nhalf + nt * 8 + 2 * t;
        *(float2*)(Cb + (size_t)(q0 + mrow + g) * HH + col) =
            make_float2(tfr(oacc[nt][0]), tfr(oacc[nt][1]));
        *(float2*)(Cb + (size_t)(q0 + mrow + g + 8) * HH + col) =
            make_float2(tfr(oacc[nt][2]), tfr(oacc[nt][3]));
    }
}

// ---------------------------------------------------------------------------
extern "C" void kernel_launch(void* const* d_in, const int* in_sizes, int n_in,
                              void* d_out, int out_size) {
    const float* x  = (const float*)d_in[0];
    const float* Wq = (const float*)d_in[1];
    const float* bq = (const float*)d_in[2];
    const float* Wk = (const float*)d_in[3];
    const float* bk = (const float*)d_in[4];
    const float* Wv = (const float*)d_in[5];
    const float* bv = (const float*)d_in[6];
    const float* Wo = (const float*)d_in[7];
    const float* bo = (const float*)d_in[8];
    float* out = (float*)d_out;

    float *pxhi, *pxlo, *pWdThi, *pWdTlo, *pWvT, *pWoT, *pbd, *pDhi, *pDlo, *pV, *pC;
    cudaGetSymbolAddress((void**)&pxhi, g_xhi);
    cudaGetSymbolAddress((void**)&pxlo, g_xlo);
    cudaGetSymbolAddress((void**)&pWdThi, g_WdThi);
    cudaGetSymbolAddress((void**)&pWdTlo, g_WdTlo);
    cudaGetSymbolAddress((void**)&pWvT, g_WvT);
    cudaGetSymbolAddress((void**)&pWoT, g_WoT);
    cudaGetSymbolAddress((void**)&pbd, g_bd);
    cudaGetSymbolAddress((void**)&pDhi, g_Dhi);
    cudaGetSymbolAddress((void**)&pDlo, g_Dlo);
    cudaGetSymbolAddress((void**)&pV, g_V);
    cudaGetSymbolAddress((void**)&pC, g_C);

    const int smem_split = 3 * 4 * 128 * GP * sizeof(float);   // 73728
    const int smem_plain = 3 * 2 * 128 * GP * sizeof(float);   // 36864
    const int smem_attn  = 2 * ASTG * sizeof(float);           // 106496
    static bool attr_set = false;
    if (!attr_set) {
        cudaFuncSetAttribute(gemm_split, cudaFuncAttributeMaxDynamicSharedMemorySize, smem_split);
        cudaFuncSetAttribute(gemm_plain<true>,  cudaFuncAttributeMaxDynamicSharedMemorySize, smem_plain);
        cudaFuncSetAttribute(gemm_plain<false>, cudaFuncAttributeMaxDynamicSharedMemorySize, smem_plain);
        cudaFuncSetAttribute(attn_mma, cudaFuncAttributeMaxDynamicSharedMemorySize, smem_attn);
        attr_set = true;
    }

    prep_x<<<MT*HH/256, 256>>>(x, bq, bk);
    prep_w<<<dim3(32, 32, 3), 256>>>(Wq, Wk, Wv, Wo);

    dim3 gg(HH/128, MT/128);  // (8, 32)
    gemm_split<<<gg, 256, smem_split>>>(pxhi, pxlo, pWdThi, pWdTlo, pbd, pDhi, pDlo);
    gemm_plain<true><<<gg, 256, smem_plain>>>(pxhi, pWvT, bv, pV);

    attn_mma<<<dim3(SS/64, BB*NHH), 256, smem_attn>>>();

    gemm_plain<false><<<gg, 256, smem_plain>>>(pC, pWoT, bo, out);
}